// round 3
// baseline (speedup 1.0000x reference)
#include <cuda_runtime.h>
#include <cstdint>

#define BB 64
#define SS 512
#define HH 1024
#define TT 17
#define NEG_INF (-3.402823466e+38f)
#define FULLM 0xffffffffu

#define FMA2(acc, a, w) \
    asm("fma.rn.f32x2 %0, %1, %2, %0;" : "+l"(acc) : "l"(a), "l"(w))

// ---------------------------------------------------------------------------
// Kernel 1: feats = x @ W^T + b.  128 blocks x 256 threads, thread = 1 row.
// W (17x1024, 68KB) resident in smem; x staged through smem coalesced.
// ---------------------------------------------------------------------------
#define KCH 32          // k per chunk
#define XS_STRIDE 36    // 32 + 4 pad (float4-aligned, conflict-free)

__global__ __launch_bounds__(256, 1)
void crf_gemm_kernel(const float* __restrict__ x,
                     const float* __restrict__ W,
                     const float* __restrict__ bvec,
                     float* __restrict__ feats)
{
    extern __shared__ float sm[];
    float* wsm = sm;                       // 17*1024 = 17408 floats
    float* xs  = sm + TT * HH;             // 256*36  =  9216 floats

    const int tid = threadIdx.x;
    const size_t rowBase = (size_t)blockIdx.x * 256;
    const float* xg = x + rowBase * HH;

    // load all of W (4352 float4, 17 per thread)
    {
        const float4* src = (const float4*)W;
        float4* dst = (float4*)wsm;
#pragma unroll
        for (int i = 0; i < 17; i++) dst[i * 256 + tid] = src[i * 256 + tid];
    }

    // prefetch chunk 0 of x: tile 256 rows x 32 k = 2048 float4, 8/thread
    float4 pf[8];
#pragma unroll
    for (int i = 0; i < 8; i++) {
        int f = i * 256 + tid;
        int r = f >> 3, cc = f & 7;
        pf[i] = __ldcs((const float4*)(xg + (size_t)r * HH) + cc);
    }

    unsigned long long acc[TT];
#pragma unroll
    for (int t = 0; t < TT; t++) acc[t] = 0ull;

    for (int c = 0; c < HH / KCH; c++) {
        __syncthreads();
#pragma unroll
        for (int i = 0; i < 8; i++) {
            int f = i * 256 + tid;
            int r = f >> 3, cc = f & 7;
            *(float4*)&xs[r * XS_STRIDE + cc * 4] = pf[i];
        }
        __syncthreads();
        if (c + 1 < HH / KCH) {
            const int kb = (c + 1) * KCH;
#pragma unroll
            for (int i = 0; i < 8; i++) {
                int f = i * 256 + tid;
                int r = f >> 3, cc = f & 7;
                pf[i] = __ldcs((const float4*)(xg + (size_t)r * HH + kb) + cc);
            }
        }
        const int kb = c * KCH;
#pragma unroll
        for (int q = 0; q < 8; q++) {
            float4 a = *(const float4*)&xs[tid * XS_STRIDE + q * 4];
            unsigned long long a01, a23;
            asm("mov.b64 %0, {%1, %2};" : "=l"(a01) : "f"(a.x), "f"(a.y));
            asm("mov.b64 %0, {%1, %2};" : "=l"(a23) : "f"(a.z), "f"(a.w));
#pragma unroll
            for (int t = 0; t < TT; t++) {
                ulonglong2 w = *(const ulonglong2*)&wsm[t * HH + kb + q * 4];
                FMA2(acc[t], a01, w.x);
                FMA2(acc[t], a23, w.y);
            }
        }
    }

    // epilogue: sum halves + bias, transpose through xs for coalesced stores
    __syncthreads();
#pragma unroll
    for (int t = 0; t < TT; t++) {
        float lo, hi;
        asm("mov.b64 {%0, %1}, %2;" : "=f"(lo), "=f"(hi) : "l"(acc[t]));
        xs[tid * TT + t] = lo + hi + __ldg(&bvec[t]);
    }
    __syncthreads();
    {
        float4* dst = (float4*)(feats + rowBase * TT);
        const float4* s4 = (const float4*)xs;
        for (int i = tid; i < 256 * TT / 4; i += 256) dst[i] = s4[i];
    }
}

// ---------------------------------------------------------------------------
// Kernel 2: masked Viterbi. Block = 256 threads (8 warps) per batch element.
// Phase 1: warp 0 runs the serial recurrence (values only), logging s_t.
// Phase 2: 8 warps compute backpointers + composed survivor maps in parallel.
// Phase 3: warp 0 chains chunk boundaries; 16 lanes backtrack in parallel.
// ---------------------------------------------------------------------------
#define SH_STRIDE 20   // s_hist row stride (floats), 80B = float4-aligned

// max + first-occurrence argmax over v[0..16]; leaves max in v[0]
__device__ __forceinline__ int tree_argmax17(float v[TT])
{
    int ix[TT];
#pragma unroll
    for (int i = 0; i < TT; i++) ix[i] = i;
#define RED17(a, b) { bool g = v[b] > v[a]; float nv = fmaxf(v[a], v[b]); \
                      ix[a] = g ? ix[b] : ix[a]; v[a] = nv; }
    RED17(0, 1)  RED17(2, 3)   RED17(4, 5)   RED17(6, 7)
    RED17(8, 9)  RED17(10, 11) RED17(12, 13) RED17(14, 15)
    RED17(0, 2)  RED17(4, 6)   RED17(8, 10)  RED17(12, 14)
    RED17(0, 4)  RED17(8, 12)
    RED17(0, 8)
    RED17(0, 16)
#undef RED17
    return ix[0];
}

__global__ __launch_bounds__(256, 1)
void crf_viterbi_kernel(const float* __restrict__ feats,
                        const float* __restrict__ trans,
                        const float* __restrict__ start_trans,
                        const float* __restrict__ end_trans,
                        const int*   __restrict__ nwords,
                        float* __restrict__ out_tags)
{
    extern __shared__ char vsm[];
    float* feats_sh = (float*)vsm;                                 // 34816 B
    float* s_hist   = (float*)(vsm + 34816);                       // 40960 B
    float* s_fin    = (float*)(vsm + 34816 + 40960);               //   128 B
    unsigned char* bp_sh = (unsigned char*)(vsm + 34816 + 40960 + 128); // 8704
    unsigned char* Csh   = bp_sh + SS * TT;                        //   512 B

    const int tid  = threadIdx.x;
    const int lane = tid & 31;
    const int wid  = tid >> 5;
    const int b    = blockIdx.x;
    const int n    = nwords[b];

    // phase 0: stage feats, prefill identity backpointers for masked steps
    {
        const float4* src = (const float4*)(feats + (size_t)b * SS * TT);
        float4* dst = (float4*)feats_sh;
        for (int i = tid; i < (SS * TT) / 4; i += 256) dst[i] = src[i];
    }
    for (int idx = tid; idx < (SS - n) * TT; idx += 256) {
        int t = n + idx / TT;
        int j = idx - (idx / TT) * TT;
        bp_sh[t * TT + j] = (unsigned char)j;
    }
    // transitions column for this lane: tc[i] = trans[i][lane]
    float tc[TT];
#pragma unroll
    for (int i = 0; i < TT; i++)
        tc[i] = (lane < TT) ? trans[i * TT + lane] : NEG_INF;
    __syncthreads();

    const int lanec = (lane < TT) ? lane : 0;

    // ---- phase 1: serial value recurrence (warp 0 only) ----
    if (wid == 0) {
        float s = (lane < TT) ? (start_trans[lane] + feats_sh[lane]) : NEG_INF;
        if (lane < TT) s_hist[lane] = s;
        for (int t = 1; t < n; t++) {
            float v[TT];
#pragma unroll
            for (int i = 0; i < TT; i++)
                v[i] = __shfl_sync(FULLM, s, i) + tc[i];
#define MX(a, c) v[a] = fmaxf(v[a], v[c]);
            MX(0, 1)  MX(2, 3)   MX(4, 5)   MX(6, 7)
            MX(8, 9)  MX(10, 11) MX(12, 13) MX(14, 15)
            MX(0, 2)  MX(4, 6)   MX(8, 10)  MX(12, 14)
            MX(0, 4)  MX(8, 12)
            MX(0, 8)
            MX(0, 16)
#undef MX
            s = v[0] + feats_sh[t * TT + lanec];
            if (lane < TT) s_hist[t * SH_STRIDE + lane] = s;
        }
        s_fin[lane] = (lane < TT) ? (s + end_trans[lane]) : NEG_INF;
    }
    __syncthreads();

    // ---- phase 2: backpointers + composed survivor maps, chunks parallel ----
    for (int c = wid; c < 16; c += 8) {
        const int t0 = 32 * c + 1;
        const int t1 = (c == 15) ? (SS - 1) : (32 * (c + 1));
        int M = lane;                       // maps tag@t -> tag@32c
        for (int t = t0; t <= t1; t++) {
            if (t < n) {
                const float* sp = &s_hist[(t - 1) * SH_STRIDE];
                float4 q0 = *(const float4*)(sp + 0);
                float4 q1 = *(const float4*)(sp + 4);
                float4 q2 = *(const float4*)(sp + 8);
                float4 q3 = *(const float4*)(sp + 12);
                float  q4 = sp[16];
                float v[TT];
                v[0]  = q0.x + tc[0];  v[1]  = q0.y + tc[1];
                v[2]  = q0.z + tc[2];  v[3]  = q0.w + tc[3];
                v[4]  = q1.x + tc[4];  v[5]  = q1.y + tc[5];
                v[6]  = q1.z + tc[6];  v[7]  = q1.w + tc[7];
                v[8]  = q2.x + tc[8];  v[9]  = q2.y + tc[9];
                v[10] = q2.z + tc[10]; v[11] = q2.w + tc[11];
                v[12] = q3.x + tc[12]; v[13] = q3.y + tc[13];
                v[14] = q4   + tc[14] * 0.0f + (q3.z + tc[14]) - q4 * 0.0f;
                v[14] = q3.z + tc[14]; v[15] = q3.w + tc[15];
                v[16] = q4   + tc[16];
                int bp = tree_argmax17(v);
                if (lane < TT) bp_sh[t * TT + lane] = (unsigned char)bp;
                M = __shfl_sync(FULLM, M, bp);   // M_new[j] = M_old[bp[j]]
            }
        }
        Csh[c * 32 + lane] = (unsigned char)M;
    }
    __syncthreads();

    // ---- phase 3: final argmax, boundary chaining, parallel backtrack ----
    if (wid == 0) {
        float v = s_fin[lane];
        int ix = (lane < TT) ? lane : 99;
#pragma unroll
        for (int off = 16; off; off >>= 1) {
            float ov = __shfl_xor_sync(FULLM, v, off);
            int   oi = __shfl_xor_sync(FULLM, ix, off);
            if (ov > v || (ov == v && oi < ix)) { v = ov; ix = oi; }
        }
        const int last_tag = ix;

        int startTag = last_tag;            // lane 15: tag @ t=511
        int cur = last_tag;
        for (int c = 15; c >= 1; c--) {
            cur = (int)Csh[c * 32 + cur];   // tag @ t = 32c
            if (lane == c - 1) startTag = cur;
        }
        __syncwarp();

        float* outT = out_tags + (size_t)b * SS;
        if (lane < 16) {
            int tag = startTag;
            const int tEnd = 32 * lane;
            const int tStart = (lane == 15) ? (SS - 1) : (32 * (lane + 1));
            for (int t = tStart; t > tEnd; t--) {
                outT[t] = (t < n) ? (float)tag : 0.0f;
                tag = (int)bp_sh[t * TT + tag];
            }
            if (lane == 0) outT[0] = (float)tag;   // n >= 1: never masked
        }
    }
}

// ---------------------------------------------------------------------------
extern "C" void kernel_launch(void* const* d_in, const int* in_sizes, int n_in,
                              void* d_out, int out_size)
{
    const float* x     = (const float*)d_in[0];
    const float* W     = (const float*)d_in[1];
    const float* bvec  = (const float*)d_in[2];
    const float* trans = (const float*)d_in[3];
    const float* st    = (const float*)d_in[4];
    const float* en    = (const float*)d_in[5];
    const int*   nw    = (const int*)d_in[6];

    float* out   = (float*)d_out;
    float* tags  = out;                     // (B,S)   = 32768 floats
    float* feats = out + BB * SS;           // (B,S,T) = 557056 floats

    const int gemmSm = (TT * HH + 256 * XS_STRIDE) * (int)sizeof(float);
    const int vitSm  = 34816 + 40960 + 128 + SS * TT + 16 * 32;

    cudaFuncSetAttribute(crf_gemm_kernel,
                         cudaFuncAttributeMaxDynamicSharedMemorySize, gemmSm);
    cudaFuncSetAttribute(crf_viterbi_kernel,
                         cudaFuncAttributeMaxDynamicSharedMemorySize, vitSm);

    crf_gemm_kernel<<<128, 256, gemmSm>>>(x, W, bvec, feats);
    crf_viterbi_kernel<<<BB, 256, vitSm>>>(feats, trans, st, en, nw, tags);
}

// round 4
// speedup vs baseline: 1.6905x; 1.6905x over previous
#include <cuda_runtime.h>
#include <cstdint>

#define BB 64
#define SS 512
#define HH 1024
#define TT 17
#define NEG_INF (-3.402823466e+38f)
#define FULLM 0xffffffffu

#define FMA2(acc, a, w) \
    asm("fma.rn.f32x2 %0, %1, %2, %0;" : "+l"(acc) : "l"(a), "l"(w))
#define ADDF2(out, a, b) \
    asm("add.rn.f32x2 %0, %1, %2;" : "=l"(out) : "l"(a), "l"(b))
#define PACK2(out, lo, hi) \
    asm("mov.b64 %0, {%1, %2};" : "=l"(out) : "f"(lo), "f"(hi))
#define DUP2(out, w) \
    asm("mov.b64 %0, {%1, %1};" : "=l"(out) : "f"(w))
#define UNPACK2(lo, hi, in) \
    asm("mov.b64 {%0, %1}, %2;" : "=f"(lo), "=f"(hi) : "l"(in))

// ---------------------------------------------------------------------------
// Kernel 1: feats = x @ W^T + b. Warp-cooperative: lane = k (mod 32),
// warp owns 8 rows as 4 f32x2 row-pairs. x loads fully coalesced.
// 512 blocks x 256 threads (8 warps x 8 rows = 64 rows/block).
// ---------------------------------------------------------------------------
__global__ __launch_bounds__(256, 1)
void crf_gemm_kernel(const float* __restrict__ x,
                     const float* __restrict__ W,
                     const float* __restrict__ bvec,
                     float* __restrict__ feats)
{
    extern __shared__ float sm[];
    float* wT      = sm;                    // [1024][17]  (17408 floats)
    float* bias_sh = sm + TT * HH;          // 17 (+3 pad)
    float* out_sh  = bias_sh + 20;          // 64*17 = 1088 floats

    const int tid  = threadIdx.x;
    const int lane = tid & 31;
    const int wid  = tid >> 5;

    if (tid < TT) bias_sh[tid] = bvec[tid];
    // W -> smem transposed: wT[k*17 + t]
    for (int i = tid; i < TT * HH; i += 256) {
        int t = i >> 10, k = i & 1023;
        wT[k * TT + t] = W[i];
    }
    __syncthreads();

    const size_t rowBase = (size_t)blockIdx.x * 64 + (size_t)wid * 8;
    const float* xp = x + rowBase * HH + lane;

    unsigned long long acc[4][TT];
#pragma unroll
    for (int p = 0; p < 4; p++)
#pragma unroll
        for (int t = 0; t < TT; t++) acc[p][t] = 0ull;

    float buf[4][8];
#pragma unroll
    for (int c = 0; c < 3; c++)
#pragma unroll
        for (int r = 0; r < 8; r++)
            buf[c][r] = __ldcs(xp + c * 32 + (size_t)r * HH);

#pragma unroll 4
    for (int c = 0; c < 32; c++) {
        if (c + 3 < 32) {
#pragma unroll
            for (int r = 0; r < 8; r++)
                buf[(c + 3) & 3][r] = __ldcs(xp + (c + 3) * 32 + (size_t)r * HH);
        }
        const float* s = buf[c & 3];
        unsigned long long x2[4];
#pragma unroll
        for (int p = 0; p < 4; p++) PACK2(x2[p], s[2 * p], s[2 * p + 1]);
        const float* wrow = &wT[(c * 32 + lane) * TT];
#pragma unroll
        for (int t = 0; t < TT; t++) {
            float w = wrow[t];
            unsigned long long w2;
            DUP2(w2, w);
#pragma unroll
            for (int p = 0; p < 4; p++) FMA2(acc[p][t], x2[p], w2);
        }
    }
    __syncthreads();   // wT dead -> reuse as reduction scratch

    // cross-lane reduction through smem, 4 warps at a time
    unsigned long long* redBase = (unsigned long long*)wT;
#pragma unroll 1
    for (int half = 0; half < 2; half++) {
        if ((wid >> 2) == half) {
            unsigned long long* myred = redBase + (size_t)(wid & 3) * 68 * 32;
#pragma unroll
            for (int p = 0; p < 4; p++)
#pragma unroll
                for (int t = 0; t < TT; t++)
                    myred[(p * TT + t) * 32 + lane] = acc[p][t];
        }
        __syncthreads();
        if ((wid >> 2) == half) {
            unsigned long long* myred = redBase + (size_t)(wid & 3) * 68 * 32;
            for (int o = lane; o < 68; o += 32) {
                unsigned long long sum = 0ull;
#pragma unroll
                for (int j = 0; j < 32; j++) {
                    int l = (j + lane) & 31;     // stagger: avoid bank conflict
                    unsigned long long v = myred[o * 32 + l];
                    ADDF2(sum, sum, v);
                }
                float lo, hi;
                UNPACK2(lo, hi, sum);
                int p = o / TT, t = o - p * TT;
                int row = wid * 8 + 2 * p;
                out_sh[row * TT + t]       = lo + bias_sh[t];
                out_sh[(row + 1) * TT + t] = hi + bias_sh[t];
            }
        }
        __syncthreads();
    }

    // coalesced block store: 1088 floats = 272 float4
    float4* dst = (float4*)(feats + (size_t)blockIdx.x * 64 * TT);
    const float4* s4 = (const float4*)out_sh;
    for (int i = tid; i < 272; i += 256) dst[i] = s4[i];
}

// ---------------------------------------------------------------------------
// Kernel 2: masked Viterbi. Block = 256 threads per batch element.
// Phase 1: warp 0 value recurrence, smem broadcast (no shuffles).
// Phase 2: 8 warps recompute backpointers + composed survivor maps.
// Phase 3: chunk-boundary chaining + 16-lane parallel backtrack.
// ---------------------------------------------------------------------------
#define SHS 20   // s_hist row stride (floats)

__global__ __launch_bounds__(256, 1)
void crf_viterbi_kernel(const float* __restrict__ feats,
                        const float* __restrict__ trans,
                        const float* __restrict__ start_trans,
                        const float* __restrict__ end_trans,
                        const int*   __restrict__ nwords,
                        float* __restrict__ out_tags)
{
    extern __shared__ char vsm[];
    float* feats_sh = (float*)vsm;                                  // 34816 B
    float* s_hist   = (float*)(vsm + 34816);                        // 40960 B
    float* s_fin    = (float*)(vsm + 34816 + 40960);                //   128 B
    unsigned char* bp_sh = (unsigned char*)(vsm + 34816 + 40960 + 128); // 8704
    unsigned char* Csh   = bp_sh + SS * TT;                         //   512 B

    const int tid  = threadIdx.x;
    const int lane = tid & 31;
    const int wid  = tid >> 5;
    const int b    = blockIdx.x;
    const int n    = nwords[b];

    // stage feats; prefill identity backpointers for masked steps
    {
        const float4* src = (const float4*)(feats + (size_t)b * SS * TT);
        float4* dstf = (float4*)feats_sh;
        for (int i = tid; i < (SS * TT) / 4; i += 256) dstf[i] = src[i];
    }
    for (int idx = tid; idx < (SS - n) * TT; idx += 256) {
        int t = n + idx / TT;
        int j = idx - (idx / TT) * TT;
        bp_sh[t * TT + j] = (unsigned char)j;
    }
    float tc[TT];
#pragma unroll
    for (int i = 0; i < TT; i++)
        tc[i] = (lane < TT) ? trans[i * TT + lane] : NEG_INF;
    __syncthreads();

    const int lanec = (lane < TT) ? lane : 0;

    // ---- phase 1: serial value recurrence via smem broadcast ----
    if (wid == 0) {
        float s = (lane < TT) ? (start_trans[lane] + feats_sh[lane]) : NEG_INF;
        if (lane < TT) s_hist[lane] = s;
        __syncwarp();
        float fnext = feats_sh[TT + lanec];
        for (int t = 1; t < n; t++) {
            const float* sp = &s_hist[(t - 1) * SHS];
            float4 q0 = *(const float4*)(sp + 0);
            float4 q1 = *(const float4*)(sp + 4);
            float4 q2 = *(const float4*)(sp + 8);
            float4 q3 = *(const float4*)(sp + 12);
            float  q4 = sp[16];
            float v0, v1, v2, v3, v4, v5, v6, v7;
            v0 = fmaxf(q0.x + tc[0],  q0.y + tc[1]);
            v1 = fmaxf(q0.z + tc[2],  q0.w + tc[3]);
            v2 = fmaxf(q1.x + tc[4],  q1.y + tc[5]);
            v3 = fmaxf(q1.z + tc[6],  q1.w + tc[7]);
            v4 = fmaxf(q2.x + tc[8],  q2.y + tc[9]);
            v5 = fmaxf(q2.z + tc[10], q2.w + tc[11]);
            v6 = fmaxf(q3.x + tc[12], q3.y + tc[13]);
            v7 = fmaxf(q3.z + tc[14], q3.w + tc[15]);
            v0 = fmaxf(v0, v1); v2 = fmaxf(v2, v3);
            v4 = fmaxf(v4, v5); v6 = fmaxf(v6, v7);
            v0 = fmaxf(v0, v2); v4 = fmaxf(v4, v6);
            v0 = fmaxf(v0, v4);
            v0 = fmaxf(v0, q4 + tc[16]);
            float f = fnext;
            if (t + 1 < SS) fnext = feats_sh[(t + 1) * TT + lanec];
            s = v0 + f;
            if (lane < TT) s_hist[t * SHS + lane] = s;
            __syncwarp();
        }
        s_fin[lane] = (lane < TT) ? (s + end_trans[lane]) : NEG_INF;
    }
    __syncthreads();

    // ---- phase 2: backpointers + composed survivor maps (parallel chunks) --
    for (int c = wid; c < 16; c += 8) {
        const int t0 = 32 * c + 1;
        const int t1 = (c == 15) ? (SS - 1) : (32 * (c + 1));
        int M = lane;
        for (int t = t0; t <= t1; t++) {
            if (t < n) {
                const float* sp = &s_hist[(t - 1) * SHS];
                float4 q0 = *(const float4*)(sp + 0);
                float4 q1 = *(const float4*)(sp + 4);
                float4 q2 = *(const float4*)(sp + 8);
                float4 q3 = *(const float4*)(sp + 12);
                float  q4 = sp[16];
                float v[TT];
                v[0]  = q0.x + tc[0];  v[1]  = q0.y + tc[1];
                v[2]  = q0.z + tc[2];  v[3]  = q0.w + tc[3];
                v[4]  = q1.x + tc[4];  v[5]  = q1.y + tc[5];
                v[6]  = q1.z + tc[6];  v[7]  = q1.w + tc[7];
                v[8]  = q2.x + tc[8];  v[9]  = q2.y + tc[9];
                v[10] = q2.z + tc[10]; v[11] = q2.w + tc[11];
                v[12] = q3.x + tc[12]; v[13] = q3.y + tc[13];
                v[14] = q3.z + tc[14]; v[15] = q3.w + tc[15];
                v[16] = q4   + tc[16];
                // value-only max tree
                float m01 = fmaxf(v[0], v[1]),  m23 = fmaxf(v[2], v[3]);
                float m45 = fmaxf(v[4], v[5]),  m67 = fmaxf(v[6], v[7]);
                float m89 = fmaxf(v[8], v[9]),  mab = fmaxf(v[10], v[11]);
                float mcd = fmaxf(v[12], v[13]), mef = fmaxf(v[14], v[15]);
                float mA = fmaxf(fmaxf(m01, m23), fmaxf(m45, m67));
                float mB = fmaxf(fmaxf(m89, mab), fmaxf(mcd, mef));
                float m  = fmaxf(fmaxf(mA, mB), v[16]);
                // first-index argmax via equality mask (exact: m is one of v[i])
                unsigned g0 = ((v[0] == m) ? 1u : 0u)  | ((v[1] == m) ? 2u : 0u)
                            | ((v[2] == m) ? 4u : 0u)  | ((v[3] == m) ? 8u : 0u);
                unsigned g1 = ((v[4] == m) ? 16u : 0u) | ((v[5] == m) ? 32u : 0u)
                            | ((v[6] == m) ? 64u : 0u) | ((v[7] == m) ? 128u : 0u);
                unsigned g2 = ((v[8] == m) ? 256u : 0u)  | ((v[9] == m) ? 512u : 0u)
                            | ((v[10] == m) ? 1024u : 0u)| ((v[11] == m) ? 2048u : 0u);
                unsigned g3 = ((v[12] == m) ? 4096u : 0u) | ((v[13] == m) ? 8192u : 0u)
                            | ((v[14] == m) ? 16384u : 0u)| ((v[15] == m) ? 32768u : 0u)
                            | ((v[16] == m) ? 65536u : 0u);
                unsigned msk = (g0 | g1) | (g2 | g3);
                int bp = __ffs(msk) - 1;
                if (lane < TT) bp_sh[t * TT + lane] = (unsigned char)bp;
                M = __shfl_sync(FULLM, M, bp);
            }
        }
        Csh[c * 32 + lane] = (unsigned char)M;
    }
    __syncthreads();

    // ---- phase 3: final argmax, boundary chaining, parallel backtrack ----
    if (wid == 0) {
        float v = s_fin[lane];
        int ix = (lane < TT) ? lane : 99;
#pragma unroll
        for (int off = 16; off; off >>= 1) {
            float ov = __shfl_xor_sync(FULLM, v, off);
            int   oi = __shfl_xor_sync(FULLM, ix, off);
            if (ov > v || (ov == v && oi < ix)) { v = ov; ix = oi; }
        }
        const int last_tag = ix;

        int startTag = last_tag;            // lane 15: tag @ t = 511
        int cur = last_tag;
        for (int c = 15; c >= 1; c--) {
            cur = (int)Csh[c * 32 + cur];   // tag @ t = 32c
            if (lane == c - 1) startTag = cur;
        }
        __syncwarp();

        float* outT = out_tags + (size_t)b * SS;
        if (lane < 16) {
            int tag = startTag;
            const int tEnd = 32 * lane;
            const int tStart = (lane == 15) ? (SS - 1) : (32 * (lane + 1));
            for (int t = tStart; t > tEnd; t--) {
                outT[t] = (t < n) ? (float)tag : 0.0f;
                tag = (int)bp_sh[t * TT + tag];
            }
            if (lane == 0) outT[0] = (float)tag;   // n >= 1: never masked
        }
    }
}

// ---------------------------------------------------------------------------
extern "C" void kernel_launch(void* const* d_in, const int* in_sizes, int n_in,
                              void* d_out, int out_size)
{
    const float* x     = (const float*)d_in[0];
    const float* W     = (const float*)d_in[1];
    const float* bvec  = (const float*)d_in[2];
    const float* trans = (const float*)d_in[3];
    const float* st    = (const float*)d_in[4];
    const float* en    = (const float*)d_in[5];
    const int*   nw    = (const int*)d_in[6];

    float* out   = (float*)d_out;
    float* tags  = out;                     // (B,S)   = 32768 floats
    float* feats = out + BB * SS;           // (B,S,T) = 557056 floats

    const int gemmSm = (TT * HH + 20 + 64 * TT) * (int)sizeof(float);  // 74064
    const int vitSm  = 34816 + 40960 + 128 + SS * TT + 16 * 32;        // 85120

    cudaFuncSetAttribute(crf_gemm_kernel,
                         cudaFuncAttributeMaxDynamicSharedMemorySize, gemmSm);
    cudaFuncSetAttribute(crf_viterbi_kernel,
                         cudaFuncAttributeMaxDynamicSharedMemorySize, vitSm);

    crf_gemm_kernel<<<512, 256, gemmSm>>>(x, W, bvec, feats);
    crf_viterbi_kernel<<<BB, 256, vitSm>>>(feats, trans, st, en, nw, tags);
}